// round 11
// baseline (speedup 1.0000x reference)
#include <cuda_runtime.h>
#include <cuda_fp16.h>
#include <cstdint>

#define NN 4096
#define BB 8
#define NBTOT (BB*NN)
#define LSC 2048.0f
#define ILSC (1.0f/2048.0f)
typedef __half hf;

__device__ __forceinline__ uint32_t pk2(float a, float b) {
    __half2 h = __floats2half2_rn(a, b);
    return *(uint32_t*)&h;
}
__device__ __forceinline__ void mma16(float* d, const uint32_t* a, uint32_t b0, uint32_t b1) {
    asm volatile("mma.sync.aligned.m16n8k16.row.col.f32.f16.f16.f32 "
        "{%0,%1,%2,%3}, {%4,%5,%6,%7}, {%8,%9}, {%0,%1,%2,%3};"
        : "+f"(d[0]), "+f"(d[1]), "+f"(d[2]), "+f"(d[3])
        : "r"(a[0]), "r"(a[1]), "r"(a[2]), "r"(a[3]), "r"(b0), "r"(b1));
}
__device__ __forceinline__ void ldfA(uint32_t* f, const hf* base, int S, int rb, int kb, int r, int q2) {
    f[0] = *(const uint32_t*)(base + (rb + r) * S + kb + q2);
    f[1] = *(const uint32_t*)(base + (rb + r + 8) * S + kb + q2);
    f[2] = *(const uint32_t*)(base + (rb + r) * S + kb + q2 + 8);
    f[3] = *(const uint32_t*)(base + (rb + r + 8) * S + kb + q2 + 8);
}

#define BUF 2097152
__device__ float SCR[8*BUF + 2*BB*NN + 512 + 16384 + 8192];

// bn coefficients from 128 per-block partials (st3[p*128+c]=sum, +64=sumsq)
__device__ __forceinline__ void bn_coef128(const float* __restrict__ st3, const float* __restrict__ g,
                                           const float* __restrict__ be, int c, float& sc, float& sh) {
    float S = 0.f, Q = 0.f;
    for (int p = 0; p < 128; p++) { S += st3[p * 128 + c]; Q += st3[p * 128 + 64 + c]; }
    const float inv = 1.0f / (float)NBTOT;
    float mean = S * inv;
    float var = Q * inv - mean * mean;
    float r = rsqrtf(var + 1e-5f);
    sc = g[c] * r; sh = be[c] - sc * mean;
}

// per-channel block-partial stats: thread holds value a for channel o; warp-reduce, stage, final.
// Call inside o-loop, then finalize after. ps/pq are smem [C*8].
__device__ __forceinline__ void stat_stage(float a, int o, int w, int lane, float* ps, float* pq) {
    float s = a, q = a * a;
    #pragma unroll
    for (int off = 16; off; off >>= 1) {
        s += __shfl_down_sync(~0u, s, off);
        q += __shfl_down_sync(~0u, q, off);
    }
    if (lane == 0) { ps[o * 8 + w] = s; pq[o * 8 + w] = q; }
}
template<int C>
__device__ __forceinline__ void stat_final(const float* ps, const float* pq, int t, int pidx, float* st3) {
    if (t < C) {
        float S = 0.f, Q = 0.f;
        #pragma unroll
        for (int i = 0; i < 8; i++) { S += ps[t * 8 + i]; Q += pq[t * 8 + i]; }
        st3[pidx * 128 + t] = S; st3[pidx * 128 + 64 + t] = Q;
    }
}

__global__ void k_conv1(const float* __restrict__ x, const float* __restrict__ w,
                        const float* __restrict__ bias, float* __restrict__ y,
                        float* __restrict__ st3) {
    __shared__ float ws[192], bs[32], ps[256], pq[256];
    int t = threadIdx.x, wd = t >> 5, lane = t & 31;
    if (t < 192) ws[t] = w[t];
    if (t < 32) bs[t] = bias[t];
    __syncthreads();
    int b = blockIdx.y, n = blockIdx.x * 256 + t;
    float in[6];
    #pragma unroll
    for (int c = 0; c < 6; c++) in[c] = x[(b * 6 + c) * NN + n];
    #pragma unroll
    for (int o = 0; o < 32; o++) {
        float a = bs[o];
        #pragma unroll
        for (int c = 0; c < 6; c++) a = fmaf(ws[o * 6 + c], in[c], a);
        y[(b * 32 + o) * NN + n] = a;
        stat_stage(a, o, wd, lane, ps, pq);
    }
    __syncthreads();
    stat_final<32>(ps, pq, t, b * 16 + blockIdx.x, st3);
}

__global__ void k_bnconv32(const float* __restrict__ yin, const float* __restrict__ st3,
                           const float* __restrict__ g, const float* __restrict__ be,
                           const float* __restrict__ w, const float* __restrict__ bias,
                           float* __restrict__ yout, float* __restrict__ st3o) {
    __shared__ float ws[1024], bs[32], sc[32], sh[32], ps[256], pq[256];
    int t = threadIdx.x, wd = t >> 5, lane = t & 31;
    for (int i = t; i < 1024; i += 256) ws[i] = w[i];
    if (t < 32) { bs[t] = bias[t]; bn_coef128(st3, g, be, t, sc[t], sh[t]); }
    __syncthreads();
    int b = blockIdx.y, n = blockIdx.x * 256 + t;
    float in[32];
    #pragma unroll
    for (int c = 0; c < 32; c++) in[c] = fmaxf(fmaf(sc[c], yin[(b * 32 + c) * NN + n], sh[c]), 0.f);
    for (int o = 0; o < 32; o++) {
        float a = bs[o];
        #pragma unroll
        for (int c = 0; c < 32; c++) a = fmaf(ws[o * 32 + c], in[c], a);
        yout[(b * 32 + o) * NN + n] = a;
        stat_stage(a, o, wd, lane, ps, pq);
    }
    __syncthreads();
    stat_final<32>(ps, pq, t, b * 16 + blockIdx.x, st3o);
}

// BN+relu -> h; q -> fp16 hi/lo planes (n-major); v -> fp16 hi/lo planes (c-major)
template<int C>
__global__ void k_bnqkv(const float* __restrict__ yin, const float* __restrict__ st3,
                        const float* __restrict__ g, const float* __restrict__ be,
                        const float* __restrict__ wqk, const float* __restrict__ wv,
                        const float* __restrict__ bv, float* __restrict__ h,
                        hf* __restrict__ qh, hf* __restrict__ ql,
                        hf* __restrict__ vh, hf* __restrict__ vl) {
    __shared__ float wq_s[C*C], wv_s[C*C], bvs[C], sc[C], sh[C];
    int t = threadIdx.x;
    for (int i = t; i < C*C; i += 256) { wq_s[i] = wqk[i]; wv_s[i] = wv[i]; }
    if (t < C) { bvs[t] = bv[t]; bn_coef128(st3, g, be, t, sc[t], sh[t]); }
    __syncthreads();
    int b = blockIdx.y, n = blockIdx.x * 256 + t;
    float in[C];
    #pragma unroll
    for (int c = 0; c < C; c++) {
        float val = fmaxf(fmaf(sc[c], yin[(b * C + c) * NN + n], sh[c]), 0.f);
        in[c] = val;
        h[(b * C + c) * NN + n] = val;
    }
    size_t qoff = ((size_t)b * NN + n) * C;
    for (int og = 0; og < C; og += 4) {
        uint32_t uh[2], ul[2];
        #pragma unroll
        for (int oo = 0; oo < 4; oo += 2) {
            float q0 = 0.f, q1 = 0.f, av0 = bvs[og+oo], av1 = bvs[og+oo+1];
            #pragma unroll
            for (int c = 0; c < C; c++) {
                q0 = fmaf(wq_s[(og+oo) * C + c], in[c], q0);
                q1 = fmaf(wq_s[(og+oo+1) * C + c], in[c], q1);
                av0 = fmaf(wv_s[(og+oo) * C + c], in[c], av0);
                av1 = fmaf(wv_s[(og+oo+1) * C + c], in[c], av1);
            }
            hf h0 = __float2half_rn(q0), h1 = __float2half_rn(q1);
            uh[oo>>1] = ((uint32_t)__half_as_ushort(h1) << 16) | __half_as_ushort(h0);
            ul[oo>>1] = pk2((q0 - __half2float(h0)) * LSC, (q1 - __half2float(h1)) * LSC);
            hf v0 = __float2half_rn(av0), v1 = __float2half_rn(av1);
            vh[(b * C + og+oo) * NN + n] = v0;
            vh[(b * C + og+oo+1) * NN + n] = v1;
            vl[(b * C + og+oo) * NN + n] = __float2half_rn((av0 - __half2float(v0)) * LSC);
            vl[(b * C + og+oo+1) * NN + n] = __float2half_rn((av1 - __half2float(v1)) * LSC);
        }
        *(uint2*)(qh + qoff + og) = make_uint2(uh[0], uh[1]);
        *(uint2*)(ql + qoff + og) = make_uint2(ul[0], ul[1]);
    }
}

// tile register buffers
template<int C, int ROWS> struct TR {
    static constexpr int NU = ROWS * C / 8 / 256;
    uint4 h[NU], l[NU];
};
template<int C, int ROWS>
__device__ __forceinline__ void tld(TR<C,ROWS>& tr, const hf* gh, const hf* gl, size_t base, int t) {
    #pragma unroll
    for (int i = 0; i < TR<C,ROWS>::NU; i++) {
        int idx = t + i * 256, row = idx / (C/8), cu = idx % (C/8);
        size_t o = base + (size_t)row * C + cu * 8;
        tr.h[i] = *(const uint4*)(gh + o);
        tr.l[i] = *(const uint4*)(gl + o);
    }
}
template<int C, int ROWS, int S>
__device__ __forceinline__ void tst(const TR<C,ROWS>& tr, hf* sh, hf* sl, int t) {
    #pragma unroll
    for (int i = 0; i < TR<C,ROWS>::NU; i++) {
        int idx = t + i * 256, row = idx / (C/8), cu = idx % (C/8);
        *(uint4*)(sh + row * S + cu * 8) = tr.h[i];
        *(uint4*)(sl + row * S + cu * 8) = tr.l[i];
    }
}
template<int C> struct TRV {
    static constexpr int NU = C * 64 / 8 / 256;
    uint4 h[NU], l[NU];
};
template<int C>
__device__ __forceinline__ void tldv(TRV<C>& tr, const hf* gh, const hf* gl, size_t bC, int n0, int t) {
    #pragma unroll
    for (int i = 0; i < TRV<C>::NU; i++) {
        int idx = t + i * 256, row = idx >> 3, cu = idx & 7;
        size_t o = (bC + row) * NN + n0 + cu * 8;
        tr.h[i] = *(const uint4*)(gh + o);
        tr.l[i] = *(const uint4*)(gl + o);
    }
}
template<int C, int SE>
__device__ __forceinline__ void tstv(const TRV<C>& tr, hf* sh, hf* sl, int t) {
    #pragma unroll
    for (int i = 0; i < TRV<C>::NU; i++) {
        int idx = t + i * 256, row = idx >> 3, cu = idx & 7;
        *(uint4*)(sh + row * SE + cu * 8) = tr.h[i];
        *(uint4*)(sl + row * SE + cu * 8) = tr.l[i];
    }
}

// ---- pass A: S = Qn x Qm^T; per-row online (M, L); prefetched B tiles ----
template<int C>
__global__ void __launch_bounds__(256) k_gramA(const hf* __restrict__ qh, const hf* __restrict__ ql,
                                               float* __restrict__ Mr, float* __restrict__ iLv) {
    constexpr int S = C + 8;
    extern __shared__ float smf[];
    float *RM = smf, *RL = smf + 256;
    hf* Ah = (hf*)(smf + 512);
    hf *Al = Ah + 128*S, *Bh = Al + 128*S, *Bl = Bh + 128*S;
    const int t = threadIdx.x, w = t >> 5, lane = t & 31;
    const int b = blockIdx.y, n0 = blockIdx.x * 128;
    const int rw = (w >> 1) * 32, cw = (w & 1) * 64;
    const int r = lane >> 2, q2 = (lane & 3) * 2;
    const size_t bN = (size_t)b * NN;
    TR<C,128> tr;
    tld<C,128>(tr, qh, ql, (bN + n0) * C, t);
    tst<C,128,S>(tr, Ah, Al, t);
    tld<C,128>(tr, qh, ql, bN * C, t);
    float Mv[4], Lv[4];
    #pragma unroll
    for (int i = 0; i < 4; i++) { Mv[i] = -1e30f; Lv[i] = 0.f; }
    for (int mt = 0; mt < 32; mt++) {
        __syncthreads();
        tst<C,128,S>(tr, Bh, Bl, t);
        __syncthreads();
        if (mt + 1 < 32) tld<C,128>(tr, qh, ql, (bN + (mt + 1) * 128) * C, t);
        float accH[2][8][4], accX[2][8][4];
        #pragma unroll
        for (int rf = 0; rf < 2; rf++)
            #pragma unroll
            for (int j = 0; j < 8; j++)
                #pragma unroll
                for (int e = 0; e < 4; e++) { accH[rf][j][e] = 0.f; accX[rf][j][e] = 0.f; }
        #pragma unroll
        for (int ks = 0; ks < C / 16; ks++) {
            int kb = ks * 16;
            uint32_t ah[2][4], al[2][4];
            #pragma unroll
            for (int rf = 0; rf < 2; rf++) {
                ldfA(ah[rf], Ah, S, rw + rf * 16, kb, r, q2);
                ldfA(al[rf], Al, S, rw + rf * 16, kb, r, q2);
            }
            #pragma unroll
            for (int j = 0; j < 8; j++) {
                int cb = cw + j * 8;
                uint32_t bh0 = *(const uint32_t*)(Bh + (cb + r) * S + kb + q2);
                uint32_t bh1 = *(const uint32_t*)(Bh + (cb + r) * S + kb + q2 + 8);
                uint32_t bl0 = *(const uint32_t*)(Bl + (cb + r) * S + kb + q2);
                uint32_t bl1 = *(const uint32_t*)(Bl + (cb + r) * S + kb + q2 + 8);
                #pragma unroll
                for (int rf = 0; rf < 2; rf++) {
                    mma16(accH[rf][j], ah[rf], bh0, bh1);
                    mma16(accX[rf][j], ah[rf], bl0, bl1);
                    mma16(accX[rf][j], al[rf], bh0, bh1);
                }
            }
        }
        #pragma unroll
        for (int rf = 0; rf < 2; rf++)
            #pragma unroll
            for (int h = 0; h < 2; h++) {
                int i = rf * 2 + h;
                float sv[16];
                #pragma unroll
                for (int j = 0; j < 8; j++) {
                    sv[2*j]   = fmaf(accX[rf][j][2*h],   ILSC, accH[rf][j][2*h]);
                    sv[2*j+1] = fmaf(accX[rf][j][2*h+1], ILSC, accH[rf][j][2*h+1]);
                }
                float tm = -1e30f;
                #pragma unroll
                for (int j = 0; j < 16; j++) tm = fmaxf(tm, sv[j]);
                float Mn = fmaxf(Mv[i], tm);
                float l = Lv[i] * __expf(Mv[i] - Mn);
                #pragma unroll
                for (int j = 0; j < 16; j++) l += __expf(sv[j] - Mn);
                Mv[i] = Mn; Lv[i] = l;
            }
    }
    #pragma unroll
    for (int i = 0; i < 4; i++)
        #pragma unroll
        for (int o = 1; o <= 2; o <<= 1) {
            float M2 = __shfl_xor_sync(~0u, Mv[i], o);
            float L2 = __shfl_xor_sync(~0u, Lv[i], o);
            float Mn = fmaxf(Mv[i], M2);
            Lv[i] = Lv[i] * __expf(Mv[i] - Mn) + L2 * __expf(M2 - Mn);
            Mv[i] = Mn;
        }
    __syncthreads();
    if ((lane & 3) == 0) {
        #pragma unroll
        for (int i = 0; i < 4; i++) {
            int row = rw + (i >> 1) * 16 + (i & 1) * 8 + r;
            RM[row * 2 + (w & 1)] = Mv[i];
            RL[row * 2 + (w & 1)] = Lv[i];
        }
    }
    __syncthreads();
    if (t < 128) {
        float M0 = RM[t*2], M1 = RM[t*2+1], L0 = RL[t*2], L1 = RL[t*2+1];
        float Mn = fmaxf(M0, M1);
        float L = L0 * __expf(M0 - Mn) + L1 * __expf(M1 - Mn);
        Mr[b * NN + n0 + t] = Mn;
        iLv[b * NN + n0 + t] = 1.0f / L;
    }
}

// ---- pass B: S' recompute + exp (E hi+lo) + col sums + xr^T = E x V; prefetched tiles ----
template<int C>
__global__ void __launch_bounds__(256) k_gramB(const hf* __restrict__ qh, const hf* __restrict__ ql,
                                               const hf* __restrict__ vhp, const hf* __restrict__ vlp,
                                               const float* __restrict__ Mr, const float* __restrict__ iLv,
                                               float* __restrict__ xrT) {
    constexpr int S = C + 8, SE = 72, NJ2 = C / 16;
    extern __shared__ float smf[];
    float *Msh = smf, *Lsh = smf + 64, *Red = smf + 128, *Sinv = smf + 384;
    hf* Qmh = (hf*)(smf + 512);
    hf *Qml = Qmh + 128*S, *Qnh = Qml + 128*S, *Qnl = Qnh + 64*S;
    hf *Vh = Qnl + 64*S, *Vl = Vh + C*SE, *Eh = Vl + C*SE, *El = Eh + 128*SE;
    const int t = threadIdx.x, w = t >> 5, lane = t & 31;
    const int b = blockIdx.y, m0 = blockIdx.x * 128;
    const int rw = (w >> 1) * 32, cw = (w & 1) * 32, cw2 = (w & 1) * (C / 2);
    const int r = lane >> 2, q2 = (lane & 3) * 2;
    const size_t bN = (size_t)b * NN, bC = (size_t)b * C;
    {
        TR<C,128> tm_;
        tld<C,128>(tm_, qh, ql, (bN + m0) * C, t);
        tst<C,128,S>(tm_, Qmh, Qml, t);
    }
    TR<C,64> trq;
    TRV<C> trv;
    float pM = 0.f, pL = 0.f;
    tld<C,64>(trq, qh, ql, bN * C, t);
    tldv<C>(trv, vhp, vlp, bC, 0, t);
    if (t < 64) { pM = Mr[b * NN + t]; pL = iLv[b * NN + t]; }
    float acc2H[2][NJ2][4], acc2X[2][NJ2][4];
    #pragma unroll
    for (int rf = 0; rf < 2; rf++)
        #pragma unroll
        for (int j = 0; j < NJ2; j++)
            #pragma unroll
            for (int e = 0; e < 4; e++) { acc2H[rf][j][e] = 0.f; acc2X[rf][j][e] = 0.f; }
    float sacc[4] = {0.f, 0.f, 0.f, 0.f};
    for (int nt = 0; nt < 64; nt++) {
        __syncthreads();
        tst<C,64,S>(trq, Qnh, Qnl, t);
        tstv<C,SE>(trv, Vh, Vl, t);
        if (t < 64) { Msh[t] = pM; Lsh[t] = pL; }
        __syncthreads();
        if (nt + 1 < 64) {
            int n1 = (nt + 1) * 64;
            tld<C,64>(trq, qh, ql, (bN + n1) * C, t);
            tldv<C>(trv, vhp, vlp, bC, n1, t);
            if (t < 64) { pM = Mr[b * NN + n1 + t]; pL = iLv[b * NN + n1 + t]; }
        }
        float accS[2][4][4], accSX[2][4][4];
        #pragma unroll
        for (int rf = 0; rf < 2; rf++)
            #pragma unroll
            for (int j = 0; j < 4; j++)
                #pragma unroll
                for (int e = 0; e < 4; e++) { accS[rf][j][e] = 0.f; accSX[rf][j][e] = 0.f; }
        #pragma unroll
        for (int ks = 0; ks < C / 16; ks++) {
            int kb = ks * 16;
            uint32_t ah[2][4], al[2][4];
            #pragma unroll
            for (int rf = 0; rf < 2; rf++) {
                ldfA(ah[rf], Qmh, S, rw + rf * 16, kb, r, q2);
                ldfA(al[rf], Qml, S, rw + rf * 16, kb, r, q2);
            }
            #pragma unroll
            for (int j = 0; j < 4; j++) {
                int cb = cw + j * 8;
                uint32_t bh0 = *(const uint32_t*)(Qnh + (cb + r) * S + kb + q2);
                uint32_t bh1 = *(const uint32_t*)(Qnh + (cb + r) * S + kb + q2 + 8);
                uint32_t bl0 = *(const uint32_t*)(Qnl + (cb + r) * S + kb + q2);
                uint32_t bl1 = *(const uint32_t*)(Qnl + (cb + r) * S + kb + q2 + 8);
                #pragma unroll
                for (int rf = 0; rf < 2; rf++) {
                    mma16(accS[rf][j], ah[rf], bh0, bh1);
                    mma16(accSX[rf][j], ah[rf], bl0, bl1);
                    mma16(accSX[rf][j], al[rf], bh0, bh1);
                }
            }
        }
        #pragma unroll
        for (int rf = 0; rf < 2; rf++)
            #pragma unroll
            for (int h = 0; h < 2; h++) {
                int row = rw + rf * 16 + h * 8 + r;
                #pragma unroll
                for (int j = 0; j < 4; j++) {
                    int col = cw + j * 8 + q2;
                    float s0 = fmaf(accSX[rf][j][2*h],   ILSC, accS[rf][j][2*h]);
                    float s1 = fmaf(accSX[rf][j][2*h+1], ILSC, accS[rf][j][2*h+1]);
                    float e0 = __expf(s0 - Msh[col])     * Lsh[col];
                    float e1 = __expf(s1 - Msh[col + 1]) * Lsh[col + 1];
                    sacc[rf * 2 + h] += e0 + e1;
                    hf eh0 = __float2half_rn(e0), eh1 = __float2half_rn(e1);
                    *(uint32_t*)(Eh + row * SE + col) =
                        ((uint32_t)__half_as_ushort(eh1) << 16) | __half_as_ushort(eh0);
                    *(uint32_t*)(El + row * SE + col) =
                        pk2((e0 - __half2float(eh0)) * LSC, (e1 - __half2float(eh1)) * LSC);
                }
            }
        __syncthreads();
        #pragma unroll
        for (int ks = 0; ks < 4; ks++) {
            int kb = ks * 16;
            uint32_t ef[2][4], efl[2][4];
            #pragma unroll
            for (int rf = 0; rf < 2; rf++) {
                ldfA(ef[rf], Eh, SE, rw + rf * 16, kb, r, q2);
                ldfA(efl[rf], El, SE, rw + rf * 16, kb, r, q2);
            }
            #pragma unroll
            for (int j = 0; j < NJ2; j++) {
                int cc = cw2 + j * 8;
                uint32_t bh0 = *(const uint32_t*)(Vh + (cc + r) * SE + kb + q2);
                uint32_t bh1 = *(const uint32_t*)(Vh + (cc + r) * SE + kb + q2 + 8);
                uint32_t bl0 = *(const uint32_t*)(Vl + (cc + r) * SE + kb + q2);
                uint32_t bl1 = *(const uint32_t*)(Vl + (cc + r) * SE + kb + q2 + 8);
                #pragma unroll
                for (int rf = 0; rf < 2; rf++) {
                    mma16(acc2H[rf][j], ef[rf], bh0, bh1);
                    mma16(acc2X[rf][j], ef[rf], bl0, bl1);
                    mma16(acc2X[rf][j], efl[rf], bh0, bh1);
                }
            }
        }
    }
    #pragma unroll
    for (int i = 0; i < 4; i++) {
        sacc[i] += __shfl_xor_sync(~0u, sacc[i], 1);
        sacc[i] += __shfl_xor_sync(~0u, sacc[i], 2);
    }
    __syncthreads();
    if ((lane & 3) == 0) {
        #pragma unroll
        for (int i = 0; i < 4; i++) {
            int row = rw + (i >> 1) * 16 + (i & 1) * 8 + r;
            Red[row * 2 + (w & 1)] = sacc[i];
        }
    }
    __syncthreads();
    if (t < 128) Sinv[t] = 1.0f / (1e-9f + Red[t*2] + Red[t*2+1]);
    __syncthreads();
    #pragma unroll
    for (int rf = 0; rf < 2; rf++)
        #pragma unroll
        for (int h = 0; h < 2; h++) {
            int row = rw + rf * 16 + h * 8 + r;
            float si = Sinv[row];
            float* dst = xrT + (bN + m0 + row) * C;
            #pragma unroll
            for (int j = 0; j < NJ2; j++) {
                int col = cw2 + j * 8 + q2;
                float u0 = fmaf(acc2X[rf][j][2*h],   ILSC, acc2H[rf][j][2*h]);
                float u1 = fmaf(acc2X[rf][j][2*h+1], ILSC, acc2H[rf][j][2*h+1]);
                *(float2*)(dst + col) = make_float2(u0 * si, u1 * si);
            }
        }
}

template<int C>
__global__ void k_diffconv(const float* __restrict__ h, const float* __restrict__ xrT,
                           const float* __restrict__ wt, const float* __restrict__ bt,
                           float* __restrict__ tp, float* __restrict__ st3o) {
    __shared__ float ws[C*C], bs[C], ps[C*8], pq[C*8];
    int t = threadIdx.x, wd = t >> 5, lane = t & 31;
    for (int i = t; i < C*C; i += 256) ws[i] = wt[i];
    if (t < C) bs[t] = bt[t];
    __syncthreads();
    int b = blockIdx.y, n = blockIdx.x * 256 + t;
    const float* xs = xrT + ((size_t)b * NN + n) * C;
    float din[C];
    #pragma unroll
    for (int c = 0; c < C; c += 4) {
        float4 xv = *(const float4*)(xs + c);
        din[c]     = h[(b * C + c) * NN + n]     - xv.x;
        din[c + 1] = h[(b * C + c + 1) * NN + n] - xv.y;
        din[c + 2] = h[(b * C + c + 2) * NN + n] - xv.z;
        din[c + 3] = h[(b * C + c + 3) * NN + n] - xv.w;
    }
    for (int o = 0; o < C; o++) {
        float a = bs[o];
        #pragma unroll
        for (int c = 0; c < C; c++) a = fmaf(ws[o * C + c], din[c], a);
        tp[(b * C + o) * NN + n] = a;
        stat_stage(a, o, wd, lane, ps, pq);
    }
    __syncthreads();
    stat_final<C>(ps, pq, t, b * 16 + blockIdx.x, st3o);
}

// out = h + relu(BN(tp)); emits per-block max partials
template<int C>
__global__ void k_resid(const float* __restrict__ h, const float* __restrict__ tp,
                        const float* __restrict__ st3, const float* __restrict__ g,
                        const float* __restrict__ be, float* __restrict__ out,
                        float* __restrict__ mxp) {
    __shared__ float scs, shs, wm[8];
    int idx0 = blockIdx.x * 256, idx = idx0 + threadIdx.x;
    int c = (idx >> 12) & (C - 1);
    if (threadIdx.x == 0) bn_coef128(st3, g, be, c, scs, shs);
    __syncthreads();
    float o = h[idx] + fmaxf(fmaf(scs, tp[idx], shs), 0.f);
    out[idx] = o;
    for (int off = 16; off; off >>= 1) o = fmaxf(o, __shfl_down_sync(~0u, o, off));
    if ((threadIdx.x & 31) == 0) wm[threadIdx.x >> 5] = o;
    __syncthreads();
    if (threadIdx.x == 0) {
        float M = wm[0];
        #pragma unroll
        for (int i = 1; i < 8; i++) M = fmaxf(M, wm[i]);
        mxp[(idx0 >> 12) * 16 + ((idx0 >> 8) & 15)] = M;
    }
}

__global__ void k_max2(const float* __restrict__ mxp, float* __restrict__ gf, int BC) {
    int t = blockIdx.x * 256 + threadIdx.x;
    if (t < BC) {
        float M = -1e30f;
        #pragma unroll
        for (int i = 0; i < 16; i++) M = fmaxf(M, mxp[t * 16 + i]);
        gf[t] = M;
    }
}

__global__ void k_concatconv(const float* __restrict__ h3, const float* __restrict__ gf1,
                             const float* __restrict__ w3, const float* __restrict__ b3,
                             float* __restrict__ y3, float* __restrict__ st3o) {
    __shared__ float ws[4096], K[64], ps[512], pq[512];
    int t = threadIdx.x, b = blockIdx.y, wd = t >> 5, lane = t & 31;
    for (int i = t; i < 4096; i += 256) ws[i] = w3[i];
    __syncthreads();
    if (t < 64) {
        float a = b3[t];
        #pragma unroll
        for (int c = 0; c < 32; c++) a = fmaf(ws[t * 64 + 32 + c], gf1[b * 32 + c], a);
        K[t] = a;
    }
    __syncthreads();
    int n = blockIdx.x * 256 + t;
    float in[32];
    #pragma unroll
    for (int c = 0; c < 32; c++) in[c] = h3[(b * 32 + c) * NN + n];
    for (int o = 0; o < 64; o++) {
        float a = K[o];
        #pragma unroll
        for (int c = 0; c < 32; c++) a = fmaf(ws[o * 64 + c], in[c], a);
        y3[(b * 64 + o) * NN + n] = a;
        stat_stage(a, o, wd, lane, ps, pq);
    }
    __syncthreads();
    stat_final<64>(ps, pq, t, b * 16 + blockIdx.x, st3o);
}

extern "C" void kernel_launch(void* const* d_in, const int* in_sizes, int n_in,
                              void* d_out, int out_size) {
    const float *x = (const float*)d_in[0], *w1 = (const float*)d_in[1], *b1 = (const float*)d_in[2],
        *g1 = (const float*)d_in[3], *be1 = (const float*)d_in[4], *w2 = (const float*)d_in[5],
        *b2 = (const float*)d_in[6], *g2 = (const float*)d_in[7], *be2 = (const float*)d_in[8],
        *a1_wqk = (const float*)d_in[9], *a1_wv = (const float*)d_in[10], *a1_bv = (const float*)d_in[11],
        *a1_wt = (const float*)d_in[12], *a1_bt = (const float*)d_in[13], *a1_g = (const float*)d_in[14],
        *a1_b = (const float*)d_in[15], *w3 = (const float*)d_in[16], *b3 = (const float*)d_in[17],
        *g3 = (const float*)d_in[18], *be3 = (const float*)d_in[19], *a2_wqk = (const float*)d_in[20],
        *a2_wv = (const float*)d_in[21], *a2_bv = (const float*)d_in[22], *a2_wt = (const float*)d_in[23],
        *a2_bt = (const float*)d_in[24], *a2_g = (const float*)d_in[25], *a2_b = (const float*)d_in[26];

    float* S = nullptr;
    cudaGetSymbolAddress((void**)&S, SCR);
    float *y1 = S, *y2 = S + BUF, *h2 = S + 2*BUF, *qkB = S + 3*BUF, *vB = S + 4*BUF,
          *xrT = S + 5*BUF, *tpb = S + 6*BUF, *h3 = S + 7*BUF;
    float *Mr = S + 8*BUF, *iL = Mr + BB*NN, *gf1 = iL + BB*NN, *st3 = gf1 + 512, *mxp = st3 + 16384;
    hf *qh = (hf*)qkB, *ql = qh + (size_t)BB*NN*64;
    hf *vh = (hf*)vB, *vl = vh + (size_t)BB*NN*64;
    float* outh = (float*)d_out;
    float* outgf = outh + BB * 64 * NN;

    int smA32 = 2048 + 4*128*40*2;
    int smA64 = 2048 + 4*128*72*2;
    int smB32 = 2048 + (2*128*40 + 2*64*40 + 2*32*72 + 2*128*72) * 2;
    int smB64 = 2048 + (2*128*72 + 2*64*72 + 2*64*72 + 2*128*72) * 2;
    cudaFuncSetAttribute(k_gramA<32>, cudaFuncAttributeMaxDynamicSharedMemorySize, smA32);
    cudaFuncSetAttribute(k_gramA<64>, cudaFuncAttributeMaxDynamicSharedMemorySize, smA64);
    cudaFuncSetAttribute(k_gramB<32>, cudaFuncAttributeMaxDynamicSharedMemorySize, smB32);
    cudaFuncSetAttribute(k_gramB<64>, cudaFuncAttributeMaxDynamicSharedMemorySize, smB64);

    dim3 gN(NN / 256, BB), gA(32, BB);
    k_conv1<<<gN, 256>>>(x, w1, b1, y1, st3);
    k_bnconv32<<<gN, 256>>>(y1, st3, g1, be1, w2, b2, y2, st3);
    k_bnqkv<32><<<gN, 256>>>(y2, st3, g2, be2, a1_wqk, a1_wv, a1_bv, h2, qh, ql, vh, vl);
    k_gramA<32><<<gA, 256, smA32>>>(qh, ql, Mr, iL);
    k_gramB<32><<<gA, 256, smB32>>>(qh, ql, vh, vl, Mr, iL, xrT);
    k_diffconv<32><<<gN, 256>>>(h2, xrT, a1_wt, a1_bt, tpb, st3);
    k_resid<32><<<BB*32*NN/256, 256>>>(h2, tpb, st3, a1_g, a1_b, h3, mxp);
    k_max2<<<1, 256>>>(mxp, gf1, BB * 32);
    k_concatconv<<<gN, 256>>>(h3, gf1, w3, b3, y2, st3);
    k_bnqkv<64><<<gN, 256>>>(y2, st3, g3, be3, a2_wqk, a2_wv, a2_bv, y1, qh, ql, vh, vl);
    k_gramA<64><<<gA, 256, smA64>>>(qh, ql, Mr, iL);
    k_gramB<64><<<gA, 256, smB64>>>(qh, ql, vh, vl, Mr, iL, xrT);
    k_diffconv<64><<<gN, 256>>>(y1, xrT, a2_wt, a2_bt, tpb, st3);
    k_resid<64><<<BB*64*NN/256, 256>>>(y1, tpb, st3, a2_g, a2_b, outh, mxp);
    k_max2<<<2, 256>>>(mxp, outgf, BB * 64);
}